// round 7
// baseline (speedup 1.0000x reference)
#include <cuda_runtime.h>
#include <cuda_bf16.h>

#define Bq 32
#define Nq 325
#define Kq 20
#define S_IN 12
#define S_OUTq 12
#define Cq 10
#define Hq 48            // 4*S_OUT
#define BNq (Bq*Nq)      // 10400

__device__ float g_wh[BNq*S_OUTq];
__device__ float g_hx[BNq*Hq];
__device__ float g_hy[BNq*Hq];
__device__ float g_wT[Cq*Hq];                   // a2_W transposed (contiguous)
__device__ double g_acc[3] = {0.0, 0.0, 0.0};   // wh_sum, dist_sum, cl_sum
__device__ int g_counter = 0;

__device__ __forceinline__ float leaky(float x){ return x >= 0.f ? x : 0.5f*x; }

// ---------------- k1: warp per (b,n) row ----------------
__global__ __launch_bounds__(256) void k1(
        const float* __restrict__ inp, const float* __restrict__ wW,
        const float* __restrict__ wb,  const float* __restrict__ a1W,
        const float* __restrict__ a2W){
    int t = threadIdx.x;
    int warp = t >> 5, lane = t & 31;
    int bn = blockIdx.x * 8 + warp;

    if (blockIdx.x == 0) {   // transpose a2_W once
        for (int i = t; i < Cq*Hq; i += 256) {
            int c = i / Hq, d = i % Hq;
            g_wT[c*Hq + d] = a2W[d*Cq + c];
        }
    }

    float whsum = 0.f;
    if (bn < BNq) {
        float xin = (lane < S_IN) ? inp[bn*S_IN + lane] : 0.f;
        float wh = (lane < S_OUTq) ? wb[lane] : 0.f;
        #pragma unroll
        for (int i = 0; i < S_IN; i++) {
            float xi = __shfl_sync(0xffffffffu, xin, i);
            if (lane < S_OUTq) wh += xi * wW[i*S_OUTq + lane];
        }
        wh = leaky(wh);
        if (lane < S_OUTq) { g_wh[bn*S_OUTq + lane] = wh; whsum = wh; }

        int d2 = 32 + (lane & 15);
        float ax = 0.f, ay = 0.f, ax2 = 0.f, ay2 = 0.f;
        #pragma unroll
        for (int s = 0; s < S_OUTq; s++) {
            float w = __shfl_sync(0xffffffffu, wh, s);
            ax  += w * a1W[s*Hq + lane];
            ay  += w * a1W[(S_OUTq+s)*Hq + lane];
            ax2 += w * a1W[s*Hq + d2];
            ay2 += w * a1W[(S_OUTq+s)*Hq + d2];
        }
        g_hx[bn*Hq + lane] = ax;
        g_hy[bn*Hq + lane] = ay;
        if (lane < 16) { g_hx[bn*Hq + d2] = ax2; g_hy[bn*Hq + d2] = ay2; }
    }
    #pragma unroll
    for (int o = 16; o; o >>= 1) whsum += __shfl_down_sync(0xffffffffu, whsum, o);
    __shared__ float sred[8];
    if (lane == 0) sred[warp] = whsum;
    __syncthreads();
    if (t == 0) {
        float s = 0.f;
        #pragma unroll
        for (int w = 0; w < 8; w++) s += sred[w];
        atomicAdd(&g_acc[0], (double)s);
    }
}

// ---------------- k2: warp per (b,n), 4 warps/block, reg-capped ----------------
__global__ __launch_bounds__(128, 10) void k2(
        const float* __restrict__ a1b, const float* __restrict__ a2b,
        const int* __restrict__ idx, float* __restrict__ out, int out_size){
    int t = threadIdx.x;
    int warp = t >> 5, lane = t & 31;
    int bn = blockIdx.x * 4 + warp;
    int b  = bn / Nq;

    __shared__ __align__(16) float s_wT[Cq*Hq];      // block-shared, broadcast reads
    __shared__ __align__(16) float s_hxb[4][Hq];     // per-warp: hx + a1_b
    __shared__ __align__(16) float s_att[4][Kq][12];
    __shared__ __align__(16) float s_wht[4][Kq][12];
    __shared__ float s_inv[4][Kq];

    // stage wT cooperatively (only cross-warp dependency)
    for (int i = t; i < 120; i += 128)
        ((float4*)s_wT)[i] = ((const float4*)g_wT)[i];

    // per-warp staging: hxb, wht rows (+norms kept in regs)
    if (lane < 12) {
        float4 hx = ((const float4*)(g_hx + bn*Hq))[lane];
        float4 bb = ((const float4*)a1b)[lane];
        ((float4*)s_hxb[warp])[lane] =
            make_float4(hx.x+bb.x, hx.y+bb.y, hx.z+bb.z, hx.w+bb.w);
    }
    int j = 0;
    float myinv = 0.f;
    if (lane < Kq) {
        j = idx[bn*Kq + lane];
        const float4* w = (const float4*)(g_wh + (size_t)(b*Nq + j)*S_OUTq);
        float4 w0 = w[0], w1 = w[1], w2 = w[2];
        ((float4*)s_wht[warp][lane])[0] = w0;
        ((float4*)s_wht[warp][lane])[1] = w1;
        ((float4*)s_wht[warp][lane])[2] = w2;
        float ss = w0.x*w0.x + w0.y*w0.y + w0.z*w0.z + w0.w*w0.w
                 + w1.x*w1.x + w1.y*w1.y + w1.z*w1.z + w1.w*w1.w
                 + w2.x*w2.x + w2.y*w2.y + w2.z*w2.z + w2.w*w2.w;
        myinv = __fdividef(1.f, sqrtf(ss) + 1e-8f);
        s_inv[warp][lane] = myinv;
    }
    __syncthreads();

    // attention row k=lane: accumulators in regs, hy straight from global,
    // wT/hxb consumed as pure warp broadcasts. Softmax entirely in registers.
    float myatt[Cq];
    if (lane < Kq) {
        const float4* hy = (const float4*)(g_hy + (size_t)(b*Nq + j)*Hq);
        float acc[Cq];
        #pragma unroll
        for (int c = 0; c < Cq; c++) acc[c] = __ldg(&a2b[c]);
        #pragma unroll 4
        for (int q = 0; q < 12; q++) {
            float4 h = hy[q];
            float4 x = ((const float4*)s_hxb[warp])[q];
            h.x = leaky(h.x + x.x); h.y = leaky(h.y + x.y);
            h.z = leaky(h.z + x.z); h.w = leaky(h.w + x.w);
            #pragma unroll
            for (int c = 0; c < Cq; c++) {
                float4 w = ((const float4*)(s_wT + c*Hq))[q];   // broadcast
                acc[c] += h.x*w.x + h.y*w.y + h.z*w.z + h.w*w.w;
            }
        }
        float m = -1e30f;
        #pragma unroll
        for (int c = 0; c < Cq; c++) { acc[c] = leaky(acc[c]); m = fmaxf(m, acc[c]); }
        float sum = 0.f;
        #pragma unroll
        for (int c = 0; c < Cq; c++) { acc[c] = __expf(acc[c] - m); sum += acc[c]; }
        float inv = __fdividef(1.f, sum);
        #pragma unroll
        for (int c = 0; c < Cq; c++) { acc[c] *= inv; myatt[c] = acc[c]; }
        ((float4*)s_att[warp][lane])[0] = make_float4(acc[0], acc[1], acc[2], acc[3]);
        ((float4*)s_att[warp][lane])[1] = make_float4(acc[4], acc[5], acc[6], acc[7]);
        ((float4*)s_att[warp][lane])[2] = make_float4(acc[8], acc[9], 0.f, 0.f);
    }
    __syncwarp();

    // pairs: full 20x20 via broadcasts; own wht row re-read (broadcast-cheap),
    // own att row stays in registers.
    float dsum = 0.f, csum = 0.f;
    if (lane < Kq) {
        float4 mw0 = ((const float4*)s_wht[warp][lane])[0];
        float4 mw1 = ((const float4*)s_wht[warp][lane])[1];
        float4 mw2 = ((const float4*)s_wht[warp][lane])[2];
        #pragma unroll 2
        for (int l = 0; l < Kq; l++) {
            float4 u0 = ((const float4*)s_wht[warp][l])[0];
            float4 u1 = ((const float4*)s_wht[warp][l])[1];
            float4 u2 = ((const float4*)s_wht[warp][l])[2];
            float d = mw0.x*u0.x + mw0.y*u0.y + mw0.z*u0.z + mw0.w*u0.w
                    + mw1.x*u1.x + mw1.y*u1.y + mw1.z*u1.z + mw1.w*u1.w
                    + mw2.x*u2.x + mw2.y*u2.y + mw2.z*u2.z + mw2.w*u2.w;
            d *= myinv * s_inv[warp][l];
            dsum += d;
            if (l != lane) {
                float4 p0 = ((const float4*)s_att[warp][l])[0];
                float4 p1 = ((const float4*)s_att[warp][l])[1];
                float4 p2 = ((const float4*)s_att[warp][l])[2];
                float pr = myatt[0]*p0.x + myatt[1]*p0.y + myatt[2]*p0.z + myatt[3]*p0.w
                         + myatt[4]*p1.x + myatt[5]*p1.y + myatt[6]*p1.z + myatt[7]*p1.w
                         + myatt[8]*p2.x + myatt[9]*p2.y;
                pr = fminf(fmaxf(pr, 1e-4f), 1.f - 1e-4f);
                float lp = __logf(pr);
                csum += (d >= 0.5f) ? -lp : lp;
            }
        }
    }
    #pragma unroll
    for (int o = 16; o; o >>= 1) {
        dsum += __shfl_down_sync(0xffffffffu, dsum, o);
        csum += __shfl_down_sync(0xffffffffu, csum, o);
    }

    // einsum: 30 lanes, 30 float4 outputs; broadcast-friendly reads
    if (lane < 30) {
        int c = lane / 3, q = lane % 3;
        float4 o = make_float4(0.f, 0.f, 0.f, 0.f);
        #pragma unroll
        for (int k = 0; k < Kq; k++) {
            float a = s_att[warp][k][c];                    // 10 consecutive words
            float4 w = ((const float4*)s_wht[warp][k])[q];  // 3 consecutive float4
            o.x += a*w.x; o.y += a*w.y; o.z += a*w.z; o.w += a*w.w;
        }
        ((float4*)(out + (size_t)bn*Cq*S_OUTq))[lane] = o;
    }

    if (lane == 0) {
        atomicAdd(&g_acc[1], (double)dsum);
        atomicAdd(&g_acc[2], (double)csum);
        __threadfence();
        int done = atomicAdd(&g_counter, 1);
        if (done == BNq - 1) {   // last warp finalizes + resets for next replay
            out[out_size - 3] = (float)(g_acc[2] / (double)BNq);
            out[out_size - 2] = (float)(g_acc[1] / (double)((long long)BNq*Kq*Kq));
            out[out_size - 1] = (float)(g_acc[0] / (double)((long long)BNq*S_OUTq));
            g_acc[0] = 0.0; g_acc[1] = 0.0; g_acc[2] = 0.0;
            g_counter = 0;
        }
    }
}

extern "C" void kernel_launch(void* const* d_in, const int* in_sizes, int n_in,
                              void* d_out, int out_size) {
    const float* input_data = (const float*)d_in[1];
    const float* wW  = (const float*)d_in[2];
    const float* wb  = (const float*)d_in[3];
    const float* a1W = (const float*)d_in[4];
    const float* a1b = (const float*)d_in[5];
    const float* a2W = (const float*)d_in[6];
    const float* a2b = (const float*)d_in[7];
    const int*   idx = (const int*)d_in[8];
    float* out = (float*)d_out;

    k1<<<(BNq + 7) / 8, 256>>>(input_data, wW, wb, a1W, a2W);
    k2<<<BNq / 4, 128>>>(a1b, a2b, idx, out, out_size);
}

// round 8
// speedup vs baseline: 1.0165x; 1.0165x over previous
#include <cuda_runtime.h>
#include <cuda_bf16.h>

#define Bq 32
#define Nq 325
#define Kq 20
#define S_IN 12
#define S_OUTq 12
#define Cq 10
#define Hq 48            // 4*S_OUT
#define BNq (Bq*Nq)      // 10400
#define K1B 1300         // k1 grid

__device__ float g_wh[BNq*S_OUTq];
__device__ float g_hx[BNq*Hq];
__device__ float g_hy[BNq*Hq];
__device__ float g_wT[Cq*Hq];    // a2_W transposed (contiguous)
__device__ float g_pd[BNq];      // per-bn dist partial
__device__ float g_pc[BNq];      // per-bn cl partial
__device__ float g_pw[K1B];      // per-k1-block wh partial

__device__ __forceinline__ float leaky(float x){ return x >= 0.f ? x : 0.5f*x; }

// ---------------- k1: warp per (b,n) row ----------------
__global__ __launch_bounds__(256) void k1(
        const float* __restrict__ inp, const float* __restrict__ wW,
        const float* __restrict__ wb,  const float* __restrict__ a1W,
        const float* __restrict__ a2W){
    int t = threadIdx.x;
    int warp = t >> 5, lane = t & 31;
    int bn = blockIdx.x * 8 + warp;

    if (blockIdx.x == 0) {   // transpose a2_W once
        for (int i = t; i < Cq*Hq; i += 256) {
            int c = i / Hq, d = i % Hq;
            g_wT[c*Hq + d] = a2W[d*Cq + c];
        }
    }

    float whsum = 0.f;
    if (bn < BNq) {
        float xin = (lane < S_IN) ? inp[bn*S_IN + lane] : 0.f;
        float wh = (lane < S_OUTq) ? wb[lane] : 0.f;
        #pragma unroll
        for (int i = 0; i < S_IN; i++) {
            float xi = __shfl_sync(0xffffffffu, xin, i);
            if (lane < S_OUTq) wh += xi * wW[i*S_OUTq + lane];
        }
        wh = leaky(wh);
        if (lane < S_OUTq) { g_wh[bn*S_OUTq + lane] = wh; whsum = wh; }

        int d2 = 32 + (lane & 15);
        float ax = 0.f, ay = 0.f, ax2 = 0.f, ay2 = 0.f;
        #pragma unroll
        for (int s = 0; s < S_OUTq; s++) {
            float w = __shfl_sync(0xffffffffu, wh, s);
            ax  += w * a1W[s*Hq + lane];
            ay  += w * a1W[(S_OUTq+s)*Hq + lane];
            ax2 += w * a1W[s*Hq + d2];
            ay2 += w * a1W[(S_OUTq+s)*Hq + d2];
        }
        g_hx[bn*Hq + lane] = ax;
        g_hy[bn*Hq + lane] = ay;
        if (lane < 16) { g_hx[bn*Hq + d2] = ax2; g_hy[bn*Hq + d2] = ay2; }
    }
    #pragma unroll
    for (int o = 16; o; o >>= 1) whsum += __shfl_down_sync(0xffffffffu, whsum, o);
    __shared__ float sred[8];
    if (lane == 0) sred[warp] = whsum;
    __syncthreads();
    if (t == 0) {
        float s = 0.f;
        #pragma unroll
        for (int w = 0; w < 8; w++) s += sred[w];
        g_pw[blockIdx.x] = s;     // plain store, no atomic
    }
}

// ---------------- k2: warp per (b,n), 4 warps/block, no atomics ----------------
__global__ __launch_bounds__(128, 10) void k2(
        const float* __restrict__ a1b, const float* __restrict__ a2b,
        const int* __restrict__ idx, float* __restrict__ out){
    int t = threadIdx.x;
    int warp = t >> 5, lane = t & 31;
    int bn = blockIdx.x * 4 + warp;
    int b  = bn / Nq;

    __shared__ __align__(16) float s_wT[Cq*Hq];      // broadcast reads
    __shared__ __align__(16) float s_hxb[4][Hq];     // per-warp: hx + a1_b
    __shared__ __align__(16) float s_att[4][Kq][12];
    __shared__ __align__(16) float s_wht[4][Kq][12];
    __shared__ float s_inv[4][Kq];
    __shared__ float s_a2b[Cq];

    for (int i = t; i < 120; i += 128)
        ((float4*)s_wT)[i] = ((const float4*)g_wT)[i];
    if (t < Cq) s_a2b[t] = a2b[t];

    if (lane < 12) {
        float4 hx = ((const float4*)(g_hx + bn*Hq))[lane];
        float4 bb = ((const float4*)a1b)[lane];
        ((float4*)s_hxb[warp])[lane] =
            make_float4(hx.x+bb.x, hx.y+bb.y, hx.z+bb.z, hx.w+bb.w);
    }
    int j = 0;
    float myinv = 0.f, myss = 0.f;
    if (lane < Kq) {
        j = idx[bn*Kq + lane];
        const float4* w = (const float4*)(g_wh + (size_t)(b*Nq + j)*S_OUTq);
        float4 w0 = w[0], w1 = w[1], w2 = w[2];
        ((float4*)s_wht[warp][lane])[0] = w0;
        ((float4*)s_wht[warp][lane])[1] = w1;
        ((float4*)s_wht[warp][lane])[2] = w2;
        myss = w0.x*w0.x + w0.y*w0.y + w0.z*w0.z + w0.w*w0.w
             + w1.x*w1.x + w1.y*w1.y + w1.z*w1.z + w1.w*w1.w
             + w2.x*w2.x + w2.y*w2.y + w2.z*w2.z + w2.w*w2.w;
        myinv = __fdividef(1.f, sqrtf(myss) + 1e-8f);
        s_inv[warp][lane] = myinv;
    }
    __syncthreads();

    // attention row k=lane: reg accumulators, hy from global, smem broadcasts
    float myatt[Cq];
    if (lane < Kq) {
        const float4* hy = (const float4*)(g_hy + (size_t)(b*Nq + j)*Hq);
        float acc[Cq];
        #pragma unroll
        for (int c = 0; c < Cq; c++) acc[c] = s_a2b[c];
        #pragma unroll 4
        for (int q = 0; q < 12; q++) {
            float4 h = hy[q];
            float4 x = ((const float4*)s_hxb[warp])[q];
            h.x = leaky(h.x + x.x); h.y = leaky(h.y + x.y);
            h.z = leaky(h.z + x.z); h.w = leaky(h.w + x.w);
            #pragma unroll
            for (int c = 0; c < Cq; c++) {
                float4 w = ((const float4*)(s_wT + c*Hq))[q];   // broadcast
                acc[c] += h.x*w.x + h.y*w.y + h.z*w.z + h.w*w.w;
            }
        }
        float m = -1e30f;
        #pragma unroll
        for (int c = 0; c < Cq; c++) { acc[c] = leaky(acc[c]); m = fmaxf(m, acc[c]); }
        float sum = 0.f;
        #pragma unroll
        for (int c = 0; c < Cq; c++) { acc[c] = __expf(acc[c] - m); sum += acc[c]; }
        float inv = __fdividef(1.f, sum);
        #pragma unroll
        for (int c = 0; c < Cq; c++) { acc[c] *= inv; myatt[c] = acc[c]; }
        ((float4*)s_att[warp][lane])[0] = make_float4(acc[0], acc[1], acc[2], acc[3]);
        ((float4*)s_att[warp][lane])[1] = make_float4(acc[4], acc[5], acc[6], acc[7]);
        ((float4*)s_att[warp][lane])[2] = make_float4(acc[8], acc[9], 0.f, 0.f);
    }
    __syncwarp();

    // rotation pairing: shift s=1..10 covers all ordered pairs with weights;
    // diagonal from registers. 10 iterations instead of 19.
    float dsum = 0.f, csum = 0.f;
    if (lane < Kq) {
        float4 mw0 = ((const float4*)s_wht[warp][lane])[0];
        float4 mw1 = ((const float4*)s_wht[warp][lane])[1];
        float4 mw2 = ((const float4*)s_wht[warp][lane])[2];
        dsum = myss * myinv * myinv;   // diagonal term
        #pragma unroll 2
        for (int s = 1; s <= 10; s++) {
            int l = lane + s; if (l >= Kq) l -= Kq;
            float4 u0 = ((const float4*)s_wht[warp][l])[0];
            float4 u1 = ((const float4*)s_wht[warp][l])[1];
            float4 u2 = ((const float4*)s_wht[warp][l])[2];
            float d = mw0.x*u0.x + mw0.y*u0.y + mw0.z*u0.z + mw0.w*u0.w
                    + mw1.x*u1.x + mw1.y*u1.y + mw1.z*u1.z + mw1.w*u1.w
                    + mw2.x*u2.x + mw2.y*u2.y + mw2.z*u2.z + mw2.w*u2.w;
            d *= myinv * s_inv[warp][l];
            float4 p0 = ((const float4*)s_att[warp][l])[0];
            float4 p1 = ((const float4*)s_att[warp][l])[1];
            float4 p2 = ((const float4*)s_att[warp][l])[2];
            float pr = myatt[0]*p0.x + myatt[1]*p0.y + myatt[2]*p0.z + myatt[3]*p0.w
                     + myatt[4]*p1.x + myatt[5]*p1.y + myatt[6]*p1.z + myatt[7]*p1.w
                     + myatt[8]*p2.x + myatt[9]*p2.y;
            pr = fminf(fmaxf(pr, 1e-4f), 1.f - 1e-4f);
            float lp = __logf(pr);
            float cl = (d >= 0.5f) ? -lp : lp;
            float wgt = (s == 10) ? 1.f : 2.f;
            dsum += wgt * d;
            csum += wgt * cl;
        }
    }
    #pragma unroll
    for (int o = 16; o; o >>= 1) {
        dsum += __shfl_down_sync(0xffffffffu, dsum, o);
        csum += __shfl_down_sync(0xffffffffu, csum, o);
    }
    if (lane == 0) { g_pd[bn] = dsum; g_pc[bn] = csum; }   // plain stores

    // einsum: 30 lanes, 30 float4 outputs
    if (lane < 30) {
        int c = lane / 3, q = lane % 3;
        float4 o = make_float4(0.f, 0.f, 0.f, 0.f);
        #pragma unroll
        for (int k = 0; k < Kq; k++) {
            float a = s_att[warp][k][c];
            float4 w = ((const float4*)s_wht[warp][k])[q];
            o.x += a*w.x; o.y += a*w.y; o.z += a*w.z; o.w += a*w.w;
        }
        ((float4*)(out + (size_t)bn*Cq*S_OUTq))[lane] = o;
    }
}

// ---------------- k3: final reduction (1 block), double accumulation ----------------
__global__ __launch_bounds__(1024) void k3(float* __restrict__ out, int out_size){
    int t = threadIdx.x;
    double d = 0.0, c = 0.0, w = 0.0;
    for (int i = t; i < BNq; i += 1024) { d += (double)g_pd[i]; c += (double)g_pc[i]; }
    for (int i = t; i < K1B; i += 1024) w += (double)g_pw[i];
    #pragma unroll
    for (int o = 16; o; o >>= 1) {
        d += __shfl_down_sync(0xffffffffu, d, o);
        c += __shfl_down_sync(0xffffffffu, c, o);
        w += __shfl_down_sync(0xffffffffu, w, o);
    }
    __shared__ double sd[32], sc[32], sw[32];
    int warp = t >> 5, lane = t & 31;
    if (lane == 0) { sd[warp] = d; sc[warp] = c; sw[warp] = w; }
    __syncthreads();
    if (warp == 0) {
        d = sd[lane]; c = sc[lane]; w = sw[lane];
        #pragma unroll
        for (int o = 16; o; o >>= 1) {
            d += __shfl_down_sync(0xffffffffu, d, o);
            c += __shfl_down_sync(0xffffffffu, c, o);
            w += __shfl_down_sync(0xffffffffu, w, o);
        }
        if (lane == 0) {
            out[out_size - 3] = (float)(c / (double)BNq);
            out[out_size - 2] = (float)(d / (double)((long long)BNq*Kq*Kq));
            out[out_size - 1] = (float)(w / (double)((long long)BNq*S_OUTq));
        }
    }
}

extern "C" void kernel_launch(void* const* d_in, const int* in_sizes, int n_in,
                              void* d_out, int out_size) {
    const float* input_data = (const float*)d_in[1];
    const float* wW  = (const float*)d_in[2];
    const float* wb  = (const float*)d_in[3];
    const float* a1W = (const float*)d_in[4];
    const float* a1b = (const float*)d_in[5];
    const float* a2W = (const float*)d_in[6];
    const float* a2b = (const float*)d_in[7];
    const int*   idx = (const int*)d_in[8];
    float* out = (float*)d_out;

    k1<<<K1B, 256>>>(input_data, wW, wb, a1W, a2W);
    k2<<<BNq / 4, 128>>>(a1b, a2b, idx, out);
    k3<<<1, 1024>>>(out, out_size);
}

// round 9
// speedup vs baseline: 1.1166x; 1.0985x over previous
#include <cuda_runtime.h>
#include <cuda_bf16.h>

#define Bq 32
#define Nq 325
#define Kq 20
#define S_IN 12
#define S_OUTq 12
#define Cq 10
#define Hq 48            // 4*S_OUT
#define BNq (Bq*Nq)      // 10400
#define K1B 650          // k1 grid (16 bn per block)
#define K2B (BNq/4)      // 2600/... 650? -> BNq/4 = 2600 blocks of 4 warps... no: 2600
// NOTE: k2 grid = BNq/4 = 2600 blocks; per-block partials
#define K2G (BNq/4)      // 2600

__device__ float g_wh[BNq*S_OUTq];
__device__ float g_hx[BNq*Hq];
__device__ float g_hy[BNq*Hq];
__device__ float g_wT[Cq*Hq];    // a2_W transposed (contiguous)
__device__ float g_pd[K2G];      // per-k2-block dist partial
__device__ float g_pc[K2G];      // per-k2-block cl partial
__device__ float g_pw[K1B];      // per-k1-block wh partial

__device__ __forceinline__ float leaky(float x){ return x >= 0.f ? x : 0.5f*x; }

// ---------------- k1: 8 threads per bn, smem weights, all-f4 ----------------
__global__ __launch_bounds__(128) void k1(
        const float* __restrict__ inp, const float* __restrict__ wW,
        const float* __restrict__ wb,  const float* __restrict__ a1W,
        const float* __restrict__ a2W){
    __shared__ __align__(16) float s_wW[S_IN*S_OUTq];   // [i][s]
    __shared__ __align__(16) float s_wb[S_OUTq];
    __shared__ __align__(16) float s_a1[S_OUTq][96];    // [s][ hx 48 | hy 48 ]
    __shared__ float s_red[4];
    int t = threadIdx.x;

    for (int i = t; i < S_IN*S_OUTq; i += 128) s_wW[i] = wW[i];
    if (t < S_OUTq) s_wb[t] = wb[t];
    for (int i = t; i < S_OUTq*96; i += 128) {
        int srow = i / 96, col = i % 96;
        s_a1[srow][col] = (col < Hq) ? a1W[srow*Hq + col]
                                     : a1W[(S_OUTq + srow)*Hq + (col - Hq)];
    }
    if (blockIdx.x == 0) {      // transpose a2_W once
        for (int i = t; i < Cq*Hq; i += 128) {
            int c = i / Hq, d = i % Hq;
            g_wT[c*Hq + d] = a2W[d*Cq + c];
        }
    }
    __syncthreads();

    int bn  = blockIdx.x * 16 + (t >> 3);   // 16 bn per block, exact fit
    int sub = t & 7;                        // 8 threads per bn, 3 f4-chunks each

    float x[S_IN];
    #pragma unroll
    for (int q = 0; q < 3; q++)
        ((float4*)x)[q] = ((const float4*)(inp + (size_t)bn*S_IN))[q];

    float wh[S_OUTq];
    #pragma unroll
    for (int s = 0; s < S_OUTq; s++) wh[s] = s_wb[s];
    #pragma unroll
    for (int i = 0; i < S_IN; i++) {
        float xi = x[i];
        #pragma unroll
        for (int q = 0; q < 3; q++) {
            float4 w = ((const float4*)(s_wW + i*S_OUTq))[q];   // broadcast
            wh[q*4+0] += xi*w.x; wh[q*4+1] += xi*w.y;
            wh[q*4+2] += xi*w.z; wh[q*4+3] += xi*w.w;
        }
    }
    float whsum = 0.f;
    #pragma unroll
    for (int s = 0; s < S_OUTq; s++) wh[s] = leaky(wh[s]);
    if (sub == 0) {
        #pragma unroll
        for (int s = 0; s < S_OUTq; s++) whsum += wh[s];
        #pragma unroll
        for (int q = 0; q < 3; q++)
            ((float4*)(g_wh + (size_t)bn*S_OUTq))[q] = ((float4*)wh)[q];
    }

    #pragma unroll
    for (int q = 0; q < 3; q++) {
        int g = sub*3 + q;                  // 0..23 over [hx|hy] f4 space
        float4 acc = make_float4(0.f, 0.f, 0.f, 0.f);
        #pragma unroll
        for (int s = 0; s < S_OUTq; s++) {
            float4 w = ((const float4*)s_a1[s])[g];   // conflict-free (8 slots)
            float v = wh[s];
            acc.x += v*w.x; acc.y += v*w.y; acc.z += v*w.z; acc.w += v*w.w;
        }
        if (g < 12) ((float4*)(g_hx + (size_t)bn*Hq))[g]      = acc;
        else        ((float4*)(g_hy + (size_t)bn*Hq))[g - 12] = acc;
    }

    #pragma unroll
    for (int o = 16; o; o >>= 1) whsum += __shfl_down_sync(0xffffffffu, whsum, o);
    if ((t & 31) == 0) s_red[t >> 5] = whsum;
    __syncthreads();
    if (t == 0) g_pw[blockIdx.x] = s_red[0] + s_red[1] + s_red[2] + s_red[3];
}

// ---------------- k2: warp per (b,n), all-lane pairs, block partials ----------------
__global__ __launch_bounds__(128, 10) void k2(
        const float* __restrict__ a1b, const float* __restrict__ a2b,
        const int* __restrict__ idx, float* __restrict__ out){
    int t = threadIdx.x;
    int warp = t >> 5, lane = t & 31;
    int bn = blockIdx.x * 4 + warp;
    int b  = bn / Nq;

    __shared__ __align__(16) float s_wT[Cq*Hq];
    __shared__ __align__(16) float s_hxb[4][Hq];
    __shared__ __align__(16) float s_att[4][Kq][12];
    __shared__ __align__(16) float s_wht[4][Kq][12];
    __shared__ float s_inv[4][Kq];
    __shared__ float s_a2b[Cq];
    __shared__ float s_rd[4], s_rc[4];

    for (int i = t; i < 120; i += 128)
        ((float4*)s_wT)[i] = ((const float4*)g_wT)[i];
    if (t < Cq) s_a2b[t] = a2b[t];

    if (lane < 12) {
        float4 hx = ((const float4*)(g_hx + (size_t)bn*Hq))[lane];
        float4 bb = ((const float4*)a1b)[lane];
        ((float4*)s_hxb[warp])[lane] =
            make_float4(hx.x+bb.x, hx.y+bb.y, hx.z+bb.z, hx.w+bb.w);
    }
    int j = 0;
    float myinv = 0.f, myss = 0.f;
    if (lane < Kq) {
        j = idx[bn*Kq + lane];
        const float4* w = (const float4*)(g_wh + (size_t)(b*Nq + j)*S_OUTq);
        float4 w0 = w[0], w1 = w[1], w2 = w[2];
        ((float4*)s_wht[warp][lane])[0] = w0;
        ((float4*)s_wht[warp][lane])[1] = w1;
        ((float4*)s_wht[warp][lane])[2] = w2;
        myss = w0.x*w0.x + w0.y*w0.y + w0.z*w0.z + w0.w*w0.w
             + w1.x*w1.x + w1.y*w1.y + w1.z*w1.z + w1.w*w1.w
             + w2.x*w2.x + w2.y*w2.y + w2.z*w2.z + w2.w*w2.w;
        myinv = __fdividef(1.f, sqrtf(myss) + 1e-8f);
        s_inv[warp][lane] = myinv;
    }
    __syncthreads();

    // attention row k=lane (reg accumulators, hy from global, smem broadcasts)
    if (lane < Kq) {
        const float4* hy = (const float4*)(g_hy + (size_t)(b*Nq + j)*Hq);
        float acc[Cq];
        #pragma unroll
        for (int c = 0; c < Cq; c++) acc[c] = s_a2b[c];
        #pragma unroll 4
        for (int q = 0; q < 12; q++) {
            float4 h = hy[q];
            float4 x = ((const float4*)s_hxb[warp])[q];
            h.x = leaky(h.x + x.x); h.y = leaky(h.y + x.y);
            h.z = leaky(h.z + x.z); h.w = leaky(h.w + x.w);
            #pragma unroll
            for (int c = 0; c < Cq; c++) {
                float4 w = ((const float4*)(s_wT + c*Hq))[q];   // broadcast
                acc[c] += h.x*w.x + h.y*w.y + h.z*w.z + h.w*w.w;
            }
        }
        float m = -1e30f;
        #pragma unroll
        for (int c = 0; c < Cq; c++) { acc[c] = leaky(acc[c]); m = fmaxf(m, acc[c]); }
        float sum = 0.f;
        #pragma unroll
        for (int c = 0; c < Cq; c++) { acc[c] = __expf(acc[c] - m); sum += acc[c]; }
        float inv = __fdividef(1.f, sum);
        #pragma unroll
        for (int c = 0; c < Cq; c++) acc[c] *= inv;
        ((float4*)s_att[warp][lane])[0] = make_float4(acc[0], acc[1], acc[2], acc[3]);
        ((float4*)s_att[warp][lane])[1] = make_float4(acc[4], acc[5], acc[6], acc[7]);
        ((float4*)s_att[warp][lane])[2] = make_float4(acc[8], acc[9], 0.f, 0.f);
    }
    __syncwarp();

    // pairs: 190 unique pairs over all 32 lanes, 6 iterations; weight 2.
    // diagonal contribution from registers (lane<20).
    float dsum = (lane < Kq) ? myss * myinv * myinv : 0.f;
    float csum = 0.f;
    #pragma unroll
    for (int it = 0; it < 6; it++) {
        int p = it*32 + lane;
        if (p < 190) {
            int s = p / Kq + 1;          // 1..10
            int k = p - (s-1)*Kq;        // 0..19
            int l = k + s; if (l >= Kq) l -= Kq;
            float4 a0 = ((const float4*)s_wht[warp][k])[0];
            float4 a1 = ((const float4*)s_wht[warp][k])[1];
            float4 a2 = ((const float4*)s_wht[warp][k])[2];
            float4 b0 = ((const float4*)s_wht[warp][l])[0];
            float4 b1 = ((const float4*)s_wht[warp][l])[1];
            float4 b2 = ((const float4*)s_wht[warp][l])[2];
            float d = a0.x*b0.x + a0.y*b0.y + a0.z*b0.z + a0.w*b0.w
                    + a1.x*b1.x + a1.y*b1.y + a1.z*b1.z + a1.w*b1.w
                    + a2.x*b2.x + a2.y*b2.y + a2.z*b2.z + a2.w*b2.w;
            d *= s_inv[warp][k] * s_inv[warp][l];
            float4 p0 = ((const float4*)s_att[warp][k])[0];
            float4 p1 = ((const float4*)s_att[warp][k])[1];
            float4 p2 = ((const float4*)s_att[warp][k])[2];
            float4 q0 = ((const float4*)s_att[warp][l])[0];
            float4 q1 = ((const float4*)s_att[warp][l])[1];
            float4 q2 = ((const float4*)s_att[warp][l])[2];
            float pr = p0.x*q0.x + p0.y*q0.y + p0.z*q0.z + p0.w*q0.w
                     + p1.x*q1.x + p1.y*q1.y + p1.z*q1.z + p1.w*q1.w
                     + p2.x*q2.x + p2.y*q2.y;   // pads are zero
            pr = fminf(fmaxf(pr, 1e-4f), 1.f - 1e-4f);
            float lp = __logf(pr);
            dsum += 2.f * d;
            csum += (d >= 0.5f) ? -2.f*lp : 2.f*lp;
        }
    }
    #pragma unroll
    for (int o = 16; o; o >>= 1) {
        dsum += __shfl_down_sync(0xffffffffu, dsum, o);
        csum += __shfl_down_sync(0xffffffffu, csum, o);
    }
    if (lane == 0) { s_rd[warp] = dsum; s_rc[warp] = csum; }

    // einsum: 30 lanes, 30 float4 outputs
    if (lane < 30) {
        int c = lane / 3, q = lane % 3;
        float4 o = make_float4(0.f, 0.f, 0.f, 0.f);
        #pragma unroll
        for (int k = 0; k < Kq; k++) {
            float a = s_att[warp][k][c];
            float4 w = ((const float4*)s_wht[warp][k])[q];
            o.x += a*w.x; o.y += a*w.y; o.z += a*w.z; o.w += a*w.w;
        }
        ((float4*)(out + (size_t)bn*Cq*S_OUTq))[lane] = o;
    }

    __syncthreads();
    if (t == 0) {
        g_pd[blockIdx.x] = s_rd[0] + s_rd[1] + s_rd[2] + s_rd[3];
        g_pc[blockIdx.x] = s_rc[0] + s_rc[1] + s_rc[2] + s_rc[3];
    }
}

// ---------------- k3: final reduction (1 block), double accumulation ----------------
__global__ __launch_bounds__(1024) void k3(float* __restrict__ out, int out_size){
    int t = threadIdx.x;
    double d = 0.0, c = 0.0, w = 0.0;
    for (int i = t; i < K2G; i += 1024) { d += (double)g_pd[i]; c += (double)g_pc[i]; }
    for (int i = t; i < K1B; i += 1024) w += (double)g_pw[i];
    #pragma unroll
    for (int o = 16; o; o >>= 1) {
        d += __shfl_down_sync(0xffffffffu, d, o);
        c += __shfl_down_sync(0xffffffffu, c, o);
        w += __shfl_down_sync(0xffffffffu, w, o);
    }
    __shared__ double sd[32], sc[32], sw[32];
    int warp = t >> 5, lane = t & 31;
    if (lane == 0) { sd[warp] = d; sc[warp] = c; sw[warp] = w; }
    __syncthreads();
    if (warp == 0) {
        d = sd[lane]; c = sc[lane]; w = sw[lane];
        #pragma unroll
        for (int o = 16; o; o >>= 1) {
            d += __shfl_down_sync(0xffffffffu, d, o);
            c += __shfl_down_sync(0xffffffffu, c, o);
            w += __shfl_down_sync(0xffffffffu, w, o);
        }
        if (lane == 0) {
            out[out_size - 3] = (float)(c / (double)BNq);
            out[out_size - 2] = (float)(d / (double)((long long)BNq*Kq*Kq));
            out[out_size - 1] = (float)(w / (double)((long long)BNq*S_OUTq));
        }
    }
}

extern "C" void kernel_launch(void* const* d_in, const int* in_sizes, int n_in,
                              void* d_out, int out_size) {
    const float* input_data = (const float*)d_in[1];
    const float* wW  = (const float*)d_in[2];
    const float* wb  = (const float*)d_in[3];
    const float* a1W = (const float*)d_in[4];
    const float* a1b = (const float*)d_in[5];
    const float* a2W = (const float*)d_in[6];
    const float* a2b = (const float*)d_in[7];
    const int*   idx = (const int*)d_in[8];
    float* out = (float*)d_out;

    k1<<<K1B, 128>>>(input_data, wW, wb, a1W, a2W);
    k2<<<K2G, 128>>>(a1b, a2b, idx, out);
    k3<<<1, 1024>>>(out, out_size);
}

// round 10
// speedup vs baseline: 1.2991x; 1.1635x over previous
#include <cuda_runtime.h>
#include <cuda_bf16.h>

#define Bq 32
#define Nq 325
#define Kq 20
#define S_IN 12
#define S_OUTq 12
#define Cq 10
#define Hq 48            // 4*S_OUT
#define BNq (Bq*Nq)      // 10400
#define K2G (BNq/4)      // 2600 k2 blocks

__device__ float g_wh[BNq*S_OUTq];
__device__ float g_hx[BNq*Hq];
__device__ float g_hy[BNq*Hq];
__device__ float g_wT[Cq*Hq];    // a2_W transposed (contiguous)
__device__ double g_acc[3] = {0.0, 0.0, 0.0};   // wh_sum, dist_sum, cl_sum
__device__ int g_counter = 0;

__device__ __forceinline__ float leaky(float x){ return x >= 0.f ? x : 0.5f*x; }

// ---------------- k1: warp per (b,n) row (R8 shape: occ 91%) ----------------
__global__ __launch_bounds__(256) void k1(
        const float* __restrict__ inp, const float* __restrict__ wW,
        const float* __restrict__ wb,  const float* __restrict__ a1W,
        const float* __restrict__ a2W){
    int t = threadIdx.x;
    int warp = t >> 5, lane = t & 31;
    int bn = blockIdx.x * 8 + warp;

    if (blockIdx.x == 0) {   // transpose a2_W once
        for (int i = t; i < Cq*Hq; i += 256) {
            int c = i / Hq, d = i % Hq;
            g_wT[c*Hq + d] = a2W[d*Cq + c];
        }
    }

    float whsum = 0.f;
    if (bn < BNq) {
        float xin = (lane < S_IN) ? inp[bn*S_IN + lane] : 0.f;
        float wh = (lane < S_OUTq) ? wb[lane] : 0.f;
        #pragma unroll
        for (int i = 0; i < S_IN; i++) {
            float xi = __shfl_sync(0xffffffffu, xin, i);
            if (lane < S_OUTq) wh += xi * wW[i*S_OUTq + lane];
        }
        wh = leaky(wh);
        if (lane < S_OUTq) { g_wh[bn*S_OUTq + lane] = wh; whsum = wh; }

        int d2 = 32 + (lane & 15);
        float ax = 0.f, ay = 0.f, ax2 = 0.f, ay2 = 0.f;
        #pragma unroll
        for (int s = 0; s < S_OUTq; s++) {
            float w = __shfl_sync(0xffffffffu, wh, s);
            ax  += w * a1W[s*Hq + lane];
            ay  += w * a1W[(S_OUTq+s)*Hq + lane];
            ax2 += w * a1W[s*Hq + d2];
            ay2 += w * a1W[(S_OUTq+s)*Hq + d2];
        }
        g_hx[bn*Hq + lane] = ax;
        g_hy[bn*Hq + lane] = ay;
        if (lane < 16) { g_hx[bn*Hq + d2] = ax2; g_hy[bn*Hq + d2] = ay2; }
    }
    #pragma unroll
    for (int o = 16; o; o >>= 1) whsum += __shfl_down_sync(0xffffffffu, whsum, o);
    __shared__ float sred[8];
    if (lane == 0) sred[warp] = whsum;
    __syncthreads();
    if (t == 0) {
        float s = 0.f;
        #pragma unroll
        for (int w = 0; w < 8; w++) s += sred[w];
        atomicAdd(&g_acc[0], (double)s);   // 1300 atomics total — negligible
    }
}

// ---------------- k2: warp per (b,n), all-lane pairs, last-block finalize ----------------
__global__ __launch_bounds__(128, 10) void k2(
        const float* __restrict__ a1b, const float* __restrict__ a2b,
        const int* __restrict__ idx, float* __restrict__ out, int out_size){
    int t = threadIdx.x;
    int warp = t >> 5, lane = t & 31;
    int bn = blockIdx.x * 4 + warp;
    int b  = bn / Nq;

    __shared__ __align__(16) float s_wT[Cq*Hq];
    __shared__ __align__(16) float s_hxb[4][Hq];
    __shared__ __align__(16) float s_att[4][Kq][12];
    __shared__ __align__(16) float s_wht[4][Kq][12];
    __shared__ float s_inv[4][Kq];
    __shared__ float s_a2b[Cq];
    __shared__ float s_rd[4], s_rc[4];

    for (int i = t; i < 120; i += 128)
        ((float4*)s_wT)[i] = ((const float4*)g_wT)[i];
    if (t < Cq) s_a2b[t] = a2b[t];

    if (lane < 12) {
        float4 hx = ((const float4*)(g_hx + (size_t)bn*Hq))[lane];
        float4 bb = ((const float4*)a1b)[lane];
        ((float4*)s_hxb[warp])[lane] =
            make_float4(hx.x+bb.x, hx.y+bb.y, hx.z+bb.z, hx.w+bb.w);
    }
    int j = 0;
    float myinv = 0.f, myss = 0.f;
    if (lane < Kq) {
        j = idx[bn*Kq + lane];
        const float4* w = (const float4*)(g_wh + (size_t)(b*Nq + j)*S_OUTq);
        float4 w0 = w[0], w1 = w[1], w2 = w[2];
        ((float4*)s_wht[warp][lane])[0] = w0;
        ((float4*)s_wht[warp][lane])[1] = w1;
        ((float4*)s_wht[warp][lane])[2] = w2;
        myss = w0.x*w0.x + w0.y*w0.y + w0.z*w0.z + w0.w*w0.w
             + w1.x*w1.x + w1.y*w1.y + w1.z*w1.z + w1.w*w1.w
             + w2.x*w2.x + w2.y*w2.y + w2.z*w2.z + w2.w*w2.w;
        myinv = __fdividef(1.f, sqrtf(myss) + 1e-8f);
        s_inv[warp][lane] = myinv;
    }
    __syncthreads();

    // attention row k=lane (reg accumulators, hy from global, smem broadcasts)
    if (lane < Kq) {
        const float4* hy = (const float4*)(g_hy + (size_t)(b*Nq + j)*Hq);
        float acc[Cq];
        #pragma unroll
        for (int c = 0; c < Cq; c++) acc[c] = s_a2b[c];
        #pragma unroll 4
        for (int q = 0; q < 12; q++) {
            float4 h = hy[q];
            float4 x = ((const float4*)s_hxb[warp])[q];
            h.x = leaky(h.x + x.x); h.y = leaky(h.y + x.y);
            h.z = leaky(h.z + x.z); h.w = leaky(h.w + x.w);
            #pragma unroll
            for (int c = 0; c < Cq; c++) {
                float4 w = ((const float4*)(s_wT + c*Hq))[q];   // broadcast
                acc[c] += h.x*w.x + h.y*w.y + h.z*w.z + h.w*w.w;
            }
        }
        float m = -1e30f;
        #pragma unroll
        for (int c = 0; c < Cq; c++) { acc[c] = leaky(acc[c]); m = fmaxf(m, acc[c]); }
        float sum = 0.f;
        #pragma unroll
        for (int c = 0; c < Cq; c++) { acc[c] = __expf(acc[c] - m); sum += acc[c]; }
        float inv = __fdividef(1.f, sum);
        #pragma unroll
        for (int c = 0; c < Cq; c++) acc[c] *= inv;
        ((float4*)s_att[warp][lane])[0] = make_float4(acc[0], acc[1], acc[2], acc[3]);
        ((float4*)s_att[warp][lane])[1] = make_float4(acc[4], acc[5], acc[6], acc[7]);
        ((float4*)s_att[warp][lane])[2] = make_float4(acc[8], acc[9], 0.f, 0.f);
    }
    __syncwarp();

    // pairs: 190 unique pairs over all 32 lanes (6 iters), weight 2; diagonal from regs
    float dsum = (lane < Kq) ? myss * myinv * myinv : 0.f;
    float csum = 0.f;
    #pragma unroll
    for (int it = 0; it < 6; it++) {
        int p = it*32 + lane;
        if (p < 190) {
            int s = p / Kq + 1;          // 1..10
            int k = p - (s-1)*Kq;        // 0..19
            int l = k + s; if (l >= Kq) l -= Kq;
            float4 a0 = ((const float4*)s_wht[warp][k])[0];
            float4 a1 = ((const float4*)s_wht[warp][k])[1];
            float4 a2 = ((const float4*)s_wht[warp][k])[2];
            float4 b0 = ((const float4*)s_wht[warp][l])[0];
            float4 b1 = ((const float4*)s_wht[warp][l])[1];
            float4 b2 = ((const float4*)s_wht[warp][l])[2];
            float d = a0.x*b0.x + a0.y*b0.y + a0.z*b0.z + a0.w*b0.w
                    + a1.x*b1.x + a1.y*b1.y + a1.z*b1.z + a1.w*b1.w
                    + a2.x*b2.x + a2.y*b2.y + a2.z*b2.z + a2.w*b2.w;
            d *= s_inv[warp][k] * s_inv[warp][l];
            float4 p0 = ((const float4*)s_att[warp][k])[0];
            float4 p1 = ((const float4*)s_att[warp][k])[1];
            float4 p2 = ((const float4*)s_att[warp][k])[2];
            float4 q0 = ((const float4*)s_att[warp][l])[0];
            float4 q1 = ((const float4*)s_att[warp][l])[1];
            float4 q2 = ((const float4*)s_att[warp][l])[2];
            float pr = p0.x*q0.x + p0.y*q0.y + p0.z*q0.z + p0.w*q0.w
                     + p1.x*q1.x + p1.y*q1.y + p1.z*q1.z + p1.w*q1.w
                     + p2.x*q2.x + p2.y*q2.y;   // pads are zero
            pr = fminf(fmaxf(pr, 1e-4f), 1.f - 1e-4f);
            float lp = __logf(pr);
            dsum += 2.f * d;
            csum += (d >= 0.5f) ? -2.f*lp : 2.f*lp;
        }
    }
    #pragma unroll
    for (int o = 16; o; o >>= 1) {
        dsum += __shfl_down_sync(0xffffffffu, dsum, o);
        csum += __shfl_down_sync(0xffffffffu, csum, o);
    }
    if (lane == 0) { s_rd[warp] = dsum; s_rc[warp] = csum; }

    // einsum: 30 lanes, 30 float4 outputs
    if (lane < 30) {
        int c = lane / 3, q = lane % 3;
        float4 o = make_float4(0.f, 0.f, 0.f, 0.f);
        #pragma unroll
        for (int k = 0; k < Kq; k++) {
            float a = s_att[warp][k][c];
            float4 w = ((const float4*)s_wht[warp][k])[q];
            o.x += a*w.x; o.y += a*w.y; o.z += a*w.z; o.w += a*w.w;
        }
        ((float4*)(out + (size_t)bn*Cq*S_OUTq))[lane] = o;
    }

    __syncthreads();
    if (t == 0) {
        atomicAdd(&g_acc[1], (double)(s_rd[0] + s_rd[1] + s_rd[2] + s_rd[3]));
        atomicAdd(&g_acc[2], (double)(s_rc[0] + s_rc[1] + s_rc[2] + s_rc[3]));
        __threadfence();
        int done = atomicAdd(&g_counter, 1);
        if (done == K2G - 1) {   // last block finalizes + resets for next replay
            out[out_size - 3] = (float)(g_acc[2] / (double)BNq);
            out[out_size - 2] = (float)(g_acc[1] / (double)((long long)BNq*Kq*Kq));
            out[out_size - 1] = (float)(g_acc[0] / (double)((long long)BNq*S_OUTq));
            g_acc[0] = 0.0; g_acc[1] = 0.0; g_acc[2] = 0.0;
            g_counter = 0;
        }
    }
}

extern "C" void kernel_launch(void* const* d_in, const int* in_sizes, int n_in,
                              void* d_out, int out_size) {
    const float* input_data = (const float*)d_in[1];
    const float* wW  = (const float*)d_in[2];
    const float* wb  = (const float*)d_in[3];
    const float* a1W = (const float*)d_in[4];
    const float* a1b = (const float*)d_in[5];
    const float* a2W = (const float*)d_in[6];
    const float* a2b = (const float*)d_in[7];
    const int*   idx = (const int*)d_in[8];
    float* out = (float*)d_out;

    k1<<<(BNq + 7) / 8, 256>>>(input_data, wW, wb, a1W, a2W);
    k2<<<K2G, 128>>>(a1b, a2b, idx, out, out_size);
}

// round 11
// speedup vs baseline: 1.4569x; 1.1215x over previous
#include <cuda_runtime.h>
#include <cuda_bf16.h>

#define Bq 32
#define Nq 325
#define Kq 20
#define S_IN 12
#define S_OUTq 12
#define Cq 10
#define Hq 48            // 4*S_OUT
#define BNq (Bq*Nq)      // 10400
#define K2G (BNq/4)      // 2600 k2 blocks
#define FULLM 0xffffffffu

__device__ float g_wh[BNq*S_OUTq];
__device__ float g_hx[BNq*Hq];
__device__ float g_hy[BNq*Hq];
__device__ float g_wT[Cq*Hq];    // a2_W transposed (contiguous)
__device__ double g_acc[3] = {0.0, 0.0, 0.0};   // wh_sum, dist_sum, cl_sum
__device__ int g_counter = 0;

__device__ __forceinline__ float leaky(float x){ return x >= 0.f ? x : 0.5f*x; }

// ---------------- k1: warp per (b,n) row (R8 shape: occ 91%) ----------------
__global__ __launch_bounds__(256) void k1(
        const float* __restrict__ inp, const float* __restrict__ wW,
        const float* __restrict__ wb,  const float* __restrict__ a1W,
        const float* __restrict__ a2W){
    int t = threadIdx.x;
    int warp = t >> 5, lane = t & 31;
    int bn = blockIdx.x * 8 + warp;

    if (blockIdx.x == 0) {   // transpose a2_W once
        for (int i = t; i < Cq*Hq; i += 256) {
            int c = i / Hq, d = i % Hq;
            g_wT[c*Hq + d] = a2W[d*Cq + c];
        }
    }

    float whsum = 0.f;
    if (bn < BNq) {
        float xin = (lane < S_IN) ? inp[bn*S_IN + lane] : 0.f;
        float wh = (lane < S_OUTq) ? wb[lane] : 0.f;
        #pragma unroll
        for (int i = 0; i < S_IN; i++) {
            float xi = __shfl_sync(FULLM, xin, i);
            if (lane < S_OUTq) wh += xi * wW[i*S_OUTq + lane];
        }
        wh = leaky(wh);
        if (lane < S_OUTq) { g_wh[bn*S_OUTq + lane] = wh; whsum = wh; }

        int d2 = 32 + (lane & 15);
        float ax = 0.f, ay = 0.f, ax2 = 0.f, ay2 = 0.f;
        #pragma unroll
        for (int s = 0; s < S_OUTq; s++) {
            float w = __shfl_sync(FULLM, wh, s);
            ax  += w * a1W[s*Hq + lane];
            ay  += w * a1W[(S_OUTq+s)*Hq + lane];
            ax2 += w * a1W[s*Hq + d2];
            ay2 += w * a1W[(S_OUTq+s)*Hq + d2];
        }
        g_hx[bn*Hq + lane] = ax;
        g_hy[bn*Hq + lane] = ay;
        if (lane < 16) { g_hx[bn*Hq + d2] = ax2; g_hy[bn*Hq + d2] = ay2; }
    }
    #pragma unroll
    for (int o = 16; o; o >>= 1) whsum += __shfl_down_sync(FULLM, whsum, o);
    __shared__ float sred[8];
    if (lane == 0) sred[warp] = whsum;
    __syncthreads();
    if (t == 0) {
        float s = 0.f;
        #pragma unroll
        for (int w = 0; w < 8; w++) s += sred[w];
        atomicAdd(&g_acc[0], (double)s);   // 1300 atomics total — negligible
    }
}

// ---------------- k2: warp per (b,n); pairs via register rotation (SHFL) ----------------
__global__ __launch_bounds__(128) void k2(
        const float* __restrict__ a1b, const float* __restrict__ a2b,
        const int* __restrict__ idx, float* __restrict__ out, int out_size){
    int t = threadIdx.x;
    int warp = t >> 5, lane = t & 31;
    int bn = blockIdx.x * 4 + warp;
    int b  = bn / Nq;

    __shared__ __align__(16) float s_wT[Cq*Hq];
    __shared__ __align__(16) float s_hxb[4][Hq];
    __shared__ __align__(16) float s_att[4][Kq][12];
    __shared__ __align__(16) float s_wht[4][Kq][12];
    __shared__ float s_a2b[Cq];
    __shared__ float s_rd[4], s_rc[4];

    for (int i = t; i < 120; i += 128)
        ((float4*)s_wT)[i] = ((const float4*)g_wT)[i];
    if (t < Cq) s_a2b[t] = a2b[t];

    if (lane < 12) {
        float4 hx = ((const float4*)(g_hx + (size_t)bn*Hq))[lane];
        float4 bb = ((const float4*)a1b)[lane];
        ((float4*)s_hxb[warp])[lane] =
            make_float4(hx.x+bb.x, hx.y+bb.y, hx.z+bb.z, hx.w+bb.w);
    }
    int j = 0;
    float w[S_OUTq];               // own wht row in regs
    float myinv = 0.f, myss = 0.f;
    #pragma unroll
    for (int i = 0; i < S_OUTq; i++) w[i] = 0.f;
    if (lane < Kq) {
        j = idx[bn*Kq + lane];
        const float4* wp = (const float4*)(g_wh + (size_t)(b*Nq + j)*S_OUTq);
        float4 w0 = wp[0], w1 = wp[1], w2 = wp[2];
        ((float4*)s_wht[warp][lane])[0] = w0;
        ((float4*)s_wht[warp][lane])[1] = w1;
        ((float4*)s_wht[warp][lane])[2] = w2;
        w[0]=w0.x; w[1]=w0.y; w[2]=w0.z; w[3]=w0.w;
        w[4]=w1.x; w[5]=w1.y; w[6]=w1.z; w[7]=w1.w;
        w[8]=w2.x; w[9]=w2.y; w[10]=w2.z; w[11]=w2.w;
        myss = 0.f;
        #pragma unroll
        for (int i = 0; i < S_OUTq; i++) myss += w[i]*w[i];
        myinv = __fdividef(1.f, sqrtf(myss) + 1e-8f);
    }
    __syncthreads();

    // attention row k=lane (reg accumulators, hy from global, smem broadcasts)
    float att[Cq];
    #pragma unroll
    for (int c = 0; c < Cq; c++) att[c] = 0.f;
    if (lane < Kq) {
        const float4* hy = (const float4*)(g_hy + (size_t)(b*Nq + j)*Hq);
        float acc[Cq];
        #pragma unroll
        for (int c = 0; c < Cq; c++) acc[c] = s_a2b[c];
        #pragma unroll 4
        for (int q = 0; q < 12; q++) {
            float4 h = hy[q];
            float4 x = ((const float4*)s_hxb[warp])[q];
            h.x = leaky(h.x + x.x); h.y = leaky(h.y + x.y);
            h.z = leaky(h.z + x.z); h.w = leaky(h.w + x.w);
            #pragma unroll
            for (int c = 0; c < Cq; c++) {
                float4 wv = ((const float4*)(s_wT + c*Hq))[q];   // broadcast
                acc[c] += h.x*wv.x + h.y*wv.y + h.z*wv.z + h.w*wv.w;
            }
        }
        float m = -1e30f;
        #pragma unroll
        for (int c = 0; c < Cq; c++) { acc[c] = leaky(acc[c]); m = fmaxf(m, acc[c]); }
        float sum = 0.f;
        #pragma unroll
        for (int c = 0; c < Cq; c++) { acc[c] = __expf(acc[c] - m); sum += acc[c]; }
        float inv = __fdividef(1.f, sum);
        #pragma unroll
        for (int c = 0; c < Cq; c++) att[c] = acc[c] * inv;
        ((float4*)s_att[warp][lane])[0] = make_float4(att[0], att[1], att[2], att[3]);
        ((float4*)s_att[warp][lane])[1] = make_float4(att[4], att[5], att[6], att[7]);
        ((float4*)s_att[warp][lane])[2] = make_float4(att[8], att[9], 0.f, 0.f);
    }
    __syncwarp();

    // pairs via incremental register rotation: at shift s, lane k holds row (k+s)%20.
    // 23 SHFLs/shift replace 12 conflicted LDS.128/iter — zero crossbar traffic.
    float dsum = (lane < Kq) ? myss * myinv * myinv : 0.f;   // diagonal
    float csum = 0.f;
    {
        int src = lane + 1; if (src >= Kq) src -= Kq;   // rotation source
        float rw[S_OUTq], ra[Cq], rinv = myinv;
        #pragma unroll
        for (int i = 0; i < S_OUTq; i++) rw[i] = w[i];
        #pragma unroll
        for (int i = 0; i < Cq; i++) ra[i] = att[i];
        #pragma unroll
        for (int s = 1; s <= 10; s++) {
            #pragma unroll
            for (int i = 0; i < S_OUTq; i++) rw[i] = __shfl_sync(FULLM, rw[i], src);
            #pragma unroll
            for (int i = 0; i < Cq; i++) ra[i] = __shfl_sync(FULLM, ra[i], src);
            rinv = __shfl_sync(FULLM, rinv, src);
            if (lane < Kq) {
                float d = 0.f;
                #pragma unroll
                for (int i = 0; i < S_OUTq; i++) d += w[i]*rw[i];
                d *= myinv * rinv;
                float pr = 0.f;
                #pragma unroll
                for (int i = 0; i < Cq; i++) pr += att[i]*ra[i];
                pr = fminf(fmaxf(pr, 1e-4f), 1.f - 1e-4f);
                float lp = __logf(pr);
                float wgt = (s == 10) ? 1.f : 2.f;
                dsum += wgt * d;
                csum += (d >= 0.5f) ? -wgt*lp : wgt*lp;
            }
        }
    }
    #pragma unroll
    for (int o = 16; o; o >>= 1) {
        dsum += __shfl_down_sync(FULLM, dsum, o);
        csum += __shfl_down_sync(FULLM, csum, o);
    }
    if (lane == 0) { s_rd[warp] = dsum; s_rc[warp] = csum; }

    // einsum: 30 lanes, 30 float4 outputs (smem reads are within-row, ~1 phase)
    if (lane < 30) {
        int c = lane / 3, q = lane % 3;
        float4 o = make_float4(0.f, 0.f, 0.f, 0.f);
        #pragma unroll
        for (int k = 0; k < Kq; k++) {
            float a = s_att[warp][k][c];
            float4 wv = ((const float4*)s_wht[warp][k])[q];
            o.x += a*wv.x; o.y += a*wv.y; o.z += a*wv.z; o.w += a*wv.w;
        }
        ((float4*)(out + (size_t)bn*Cq*S_OUTq))[lane] = o;
    }

    __syncthreads();
    if (t == 0) {
        atomicAdd(&g_acc[1], (double)(s_rd[0] + s_rd[1] + s_rd[2] + s_rd[3]));
        atomicAdd(&g_acc[2], (double)(s_rc[0] + s_rc[1] + s_rc[2] + s_rc[3]));
        __threadfence();
        int done = atomicAdd(&g_counter, 1);
        if (done == K2G - 1) {   // last block finalizes + resets for next replay
            out[out_size - 3] = (float)(g_acc[2] / (double)BNq);
            out[out_size - 2] = (float)(g_acc[1] / (double)((long long)BNq*Kq*Kq));
            out[out_size - 1] = (float)(g_acc[0] / (double)((long long)BNq*S_OUTq));
            g_acc[0] = 0.0; g_acc[1] = 0.0; g_acc[2] = 0.0;
            g_counter = 0;
        }
    }
}

extern "C" void kernel_launch(void* const* d_in, const int* in_sizes, int n_in,
                              void* d_out, int out_size) {
    const float* input_data = (const float*)d_in[1];
    const float* wW  = (const float*)d_in[2];
    const float* wb  = (const float*)d_in[3];
    const float* a1W = (const float*)d_in[4];
    const float* a1b = (const float*)d_in[5];
    const float* a2W = (const float*)d_in[6];
    const float* a2b = (const float*)d_in[7];
    const int*   idx = (const int*)d_in[8];
    float* out = (float*)d_out;

    k1<<<(BNq + 7) / 8, 256>>>(input_data, wW, wb, a1W, a2W);
    k2<<<K2G, 128>>>(a1b, a2b, idx, out, out_size);
}